// round 4
// baseline (speedup 1.0000x reference)
#include <cuda_runtime.h>
#include <cuda_bf16.h>

// Masked mean: mean of (x - y) where x > y, over 32M fp32 elements.
// Exact-partition fast path: 2^18 threads x 32 float4-pairs each, zero tail,
// zero bounds checks, 8x front-batched LDG.128 streaming loads per pass.
// Last-block-done finalize with self-resetting __device__ globals.

__device__ float               g_sum;     // zero-initialized at load
__device__ unsigned long long  g_cnt;
__device__ unsigned int        g_ticket;

#define THREADS 256
#define BLOCKS  1024
#define TOTAL   (THREADS * BLOCKS)   // 262144 = 2^18

__device__ __forceinline__ void acc4(float4 xv, float4 yv,
                                     float& fs, unsigned int& cnt) {
    float d0 = xv.x - yv.x, d1 = xv.y - yv.y;
    float d2 = xv.z - yv.z, d3 = xv.w - yv.w;
    fs += fmaxf(d0, 0.0f) + fmaxf(d1, 0.0f)
        + fmaxf(d2, 0.0f) + fmaxf(d3, 0.0f);
    cnt += (d0 > 0.0f) + (d1 > 0.0f) + (d2 > 0.0f) + (d3 > 0.0f);
}

__global__ __launch_bounds__(THREADS) void fused_reduce_kernel(
    const float4* __restrict__ x4,
    const float4* __restrict__ y4,
    int n4,
    float* __restrict__ out)
{
    float fs0 = 0.0f, fs1 = 0.0f;
    unsigned int cnt = 0;

    const int tid = blockIdx.x * THREADS + threadIdx.x;

    if (n4 == TOTAL * 32) {
        // ---- fast path: exactly 32 iters/thread, 4 passes x unroll 8 ----
        #pragma unroll
        for (int p = 0; p < 4; p++) {
            int base = tid + p * (8 * TOTAL);
            float4 xa[8], ya[8];
            #pragma unroll
            for (int k = 0; k < 8; k++) xa[k] = __ldcs(&x4[base + k * TOTAL]);
            #pragma unroll
            for (int k = 0; k < 8; k++) ya[k] = __ldcs(&y4[base + k * TOTAL]);
            #pragma unroll
            for (int k = 0; k < 8; k++) {
                if (k & 1) acc4(xa[k], ya[k], fs1, cnt);
                else       acc4(xa[k], ya[k], fs0, cnt);
            }
        }
    } else {
        // ---- generic fallback ----
        for (int i = tid; i < n4; i += TOTAL) {
            float4 xv = __ldcs(&x4[i]);
            float4 yv = __ldcs(&y4[i]);
            acc4(xv, yv, fs0, cnt);
        }
    }

    float fsum = fs0 + fs1;

    // warp reduce
    #pragma unroll
    for (int off = 16; off > 0; off >>= 1) {
        fsum += __shfl_down_sync(0xFFFFFFFFu, fsum, off);
        cnt  += __shfl_down_sync(0xFFFFFFFFu, cnt,  off);
    }

    __shared__ float        s_sum[8];
    __shared__ unsigned int s_cnt[8];
    __shared__ bool         s_last;
    int lane = threadIdx.x & 31;
    int wid  = threadIdx.x >> 5;
    if (lane == 0) { s_sum[wid] = fsum; s_cnt[wid] = cnt; }
    __syncthreads();

    if (wid == 0) {
        fsum = (lane < 8) ? s_sum[lane] : 0.0f;
        cnt  = (lane < 8) ? s_cnt[lane] : 0u;
        #pragma unroll
        for (int off = 4; off > 0; off >>= 1) {
            fsum += __shfl_down_sync(0xFFFFFFFFu, fsum, off);
            cnt  += __shfl_down_sync(0xFFFFFFFFu, cnt,  off);
        }
        if (lane == 0) {
            atomicAdd(&g_sum, fsum);
            atomicAdd(&g_cnt, (unsigned long long)cnt);
            __threadfence();
            unsigned int t = atomicAdd(&g_ticket, 1u);
            s_last = (t == gridDim.x - 1);
        }
    }
    __syncthreads();

    // Last block: write result, reset globals for next graph replay.
    if (s_last && threadIdx.x == 0) {
        __threadfence();
        float              fs = g_sum;
        unsigned long long c  = g_cnt;
        out[0] = (c > 0ull) ? (fs / (float)c) : 0.0f;
        g_sum    = 0.0f;
        g_cnt    = 0ull;
        g_ticket = 0u;
        __threadfence();
    }
}

extern "C" void kernel_launch(void* const* d_in, const int* in_sizes, int n_in,
                              void* d_out, int out_size) {
    const float* x = (const float*)d_in[0];
    const float* y = (const float*)d_in[1];
    float* out = (float*)d_out;

    int n  = in_sizes[0];      // 33554432, divisible by 4
    int n4 = n >> 2;

    fused_reduce_kernel<<<BLOCKS, THREADS>>>(
        (const float4*)x, (const float4*)y, n4, out);
}

// round 5
// speedup vs baseline: 1.0740x; 1.0740x over previous
#include <cuda_runtime.h>
#include <cuda_bf16.h>

// Masked mean: mean of (x - y) where x > y, over 32M fp32 elements.
// Best-measured config (R3): 1184 CTAs (148 SMs x 8) x 256 threads,
// 4x-unrolled grid-stride, 8 streaming LDG.128s in flight (MLP_p1=8 --
// higher front-batching regresses via cross-CTA L1tex queue contention).
// Last-block-done finalize with self-resetting __device__ globals.

__device__ float               g_sum;     // zero-initialized at load
__device__ unsigned long long  g_cnt;
__device__ unsigned int        g_ticket;

__device__ __forceinline__ void acc4(float4 xv, float4 yv,
                                     float& fs, unsigned int& cnt) {
    float d0 = xv.x - yv.x, d1 = xv.y - yv.y;
    float d2 = xv.z - yv.z, d3 = xv.w - yv.w;
    fs += fmaxf(d0, 0.0f) + fmaxf(d1, 0.0f)
        + fmaxf(d2, 0.0f) + fmaxf(d3, 0.0f);
    cnt += (d0 > 0.0f) + (d1 > 0.0f) + (d2 > 0.0f) + (d3 > 0.0f);
}

__global__ __launch_bounds__(256) void fused_reduce_kernel(
    const float4* __restrict__ x4,
    const float4* __restrict__ y4,
    int n4,
    float* __restrict__ out)
{
    float fs0 = 0.0f, fs1 = 0.0f;
    unsigned int cnt = 0;

    const int stride = gridDim.x * blockDim.x;
    int i = blockIdx.x * blockDim.x + threadIdx.x;

    // main loop: 4x unrolled, x/y pairs interleaved (8 loads in flight)
    for (; i + 3 * stride < n4; i += 4 * stride) {
        float4 xa = __ldcs(&x4[i]);
        float4 ya = __ldcs(&y4[i]);
        float4 xb = __ldcs(&x4[i +     stride]);
        float4 yb = __ldcs(&y4[i +     stride]);
        float4 xc = __ldcs(&x4[i + 2 * stride]);
        float4 yc = __ldcs(&y4[i + 2 * stride]);
        float4 xd = __ldcs(&x4[i + 3 * stride]);
        float4 yd = __ldcs(&y4[i + 3 * stride]);

        acc4(xa, ya, fs0, cnt);
        acc4(xb, yb, fs1, cnt);
        acc4(xc, yc, fs0, cnt);
        acc4(xd, yd, fs1, cnt);
    }

    // tail
    for (; i < n4; i += stride) {
        float4 xv = __ldcs(&x4[i]);
        float4 yv = __ldcs(&y4[i]);
        acc4(xv, yv, fs0, cnt);
    }

    float fsum = fs0 + fs1;

    // warp reduce
    #pragma unroll
    for (int off = 16; off > 0; off >>= 1) {
        fsum += __shfl_down_sync(0xFFFFFFFFu, fsum, off);
        cnt  += __shfl_down_sync(0xFFFFFFFFu, cnt,  off);
    }

    __shared__ float        s_sum[8];
    __shared__ unsigned int s_cnt[8];
    __shared__ bool         s_last;
    int lane = threadIdx.x & 31;
    int wid  = threadIdx.x >> 5;
    if (lane == 0) { s_sum[wid] = fsum; s_cnt[wid] = cnt; }
    __syncthreads();

    if (wid == 0) {
        fsum = (lane < 8) ? s_sum[lane] : 0.0f;
        cnt  = (lane < 8) ? s_cnt[lane] : 0u;
        #pragma unroll
        for (int off = 4; off > 0; off >>= 1) {
            fsum += __shfl_down_sync(0xFFFFFFFFu, fsum, off);
            cnt  += __shfl_down_sync(0xFFFFFFFFu, cnt,  off);
        }
        if (lane == 0) {
            atomicAdd(&g_sum, fsum);
            atomicAdd(&g_cnt, (unsigned long long)cnt);
            __threadfence();
            unsigned int t = atomicAdd(&g_ticket, 1u);
            s_last = (t == gridDim.x - 1);
        }
    }
    __syncthreads();

    // Last block: write result, reset globals for next graph replay.
    if (s_last && threadIdx.x == 0) {
        __threadfence();
        float              fs = g_sum;
        unsigned long long c  = g_cnt;
        out[0] = (c > 0ull) ? (fs / (float)c) : 0.0f;
        g_sum    = 0.0f;
        g_cnt    = 0ull;
        g_ticket = 0u;
        __threadfence();
    }
}

extern "C" void kernel_launch(void* const* d_in, const int* in_sizes, int n_in,
                              void* d_out, int out_size) {
    const float* x = (const float*)d_in[0];
    const float* y = (const float*)d_in[1];
    float* out = (float*)d_out;

    int n  = in_sizes[0];      // 33554432, divisible by 4
    int n4 = n >> 2;

    const int threads = 256;
    const int blocks  = 148 * 8;   // 1184 CTAs -- balanced waves on 148 SMs
    fused_reduce_kernel<<<blocks, threads>>>(
        (const float4*)x, (const float4*)y, n4, out);
}

// round 6
// speedup vs baseline: 1.0793x; 1.0049x over previous
#include <cuda_runtime.h>
#include <cuda_bf16.h>

// Masked mean: mean of (x - y) where x > y, over 32M fp32 elements.
// Converged config (best measured: 43.8us kernel, DRAM 78.4%):
// 1184 CTAs (148 SMs x 8) x 256 threads, 4x-unrolled grid-stride,
// front-batched x-loads then y-loads (4+4 LDG.128 bursts), __ldcs
// streaming (touch-once). Last-block-done finalize with self-resetting
// __device__ globals (graph-replay safe, single launch).

__device__ float               g_sum;     // zero-initialized at load
__device__ unsigned long long  g_cnt;
__device__ unsigned int        g_ticket;

__global__ __launch_bounds__(256) void fused_reduce_kernel(
    const float4* __restrict__ x4,
    const float4* __restrict__ y4,
    int n4,
    float* __restrict__ out)
{
    float fs0 = 0.0f, fs1 = 0.0f;
    unsigned int cnt = 0;

    const int stride = gridDim.x * blockDim.x;
    int i = blockIdx.x * blockDim.x + threadIdx.x;

    // main loop: 4x unrolled, 4 x-loads batched then 4 y-loads batched
    for (; i + 3 * stride < n4; i += 4 * stride) {
        float4 xa = __ldcs(&x4[i]);
        float4 xb = __ldcs(&x4[i +     stride]);
        float4 xc = __ldcs(&x4[i + 2 * stride]);
        float4 xd = __ldcs(&x4[i + 3 * stride]);
        float4 ya = __ldcs(&y4[i]);
        float4 yb = __ldcs(&y4[i +     stride]);
        float4 yc = __ldcs(&y4[i + 2 * stride]);
        float4 yd = __ldcs(&y4[i + 3 * stride]);

        float a0 = xa.x - ya.x, a1 = xa.y - ya.y, a2 = xa.z - ya.z, a3 = xa.w - ya.w;
        float b0 = xb.x - yb.x, b1 = xb.y - yb.y, b2 = xb.z - yb.z, b3 = xb.w - yb.w;
        float c0 = xc.x - yc.x, c1 = xc.y - yc.y, c2 = xc.z - yc.z, c3 = xc.w - yc.w;
        float e0 = xd.x - yd.x, e1 = xd.y - yd.y, e2 = xd.z - yd.z, e3 = xd.w - yd.w;

        fs0 += fmaxf(a0, 0.0f) + fmaxf(a1, 0.0f) + fmaxf(a2, 0.0f) + fmaxf(a3, 0.0f);
        fs1 += fmaxf(b0, 0.0f) + fmaxf(b1, 0.0f) + fmaxf(b2, 0.0f) + fmaxf(b3, 0.0f);
        fs0 += fmaxf(c0, 0.0f) + fmaxf(c1, 0.0f) + fmaxf(c2, 0.0f) + fmaxf(c3, 0.0f);
        fs1 += fmaxf(e0, 0.0f) + fmaxf(e1, 0.0f) + fmaxf(e2, 0.0f) + fmaxf(e3, 0.0f);

        cnt += (a0 > 0.0f) + (a1 > 0.0f) + (a2 > 0.0f) + (a3 > 0.0f)
             + (b0 > 0.0f) + (b1 > 0.0f) + (b2 > 0.0f) + (b3 > 0.0f)
             + (c0 > 0.0f) + (c1 > 0.0f) + (c2 > 0.0f) + (c3 > 0.0f)
             + (e0 > 0.0f) + (e1 > 0.0f) + (e2 > 0.0f) + (e3 > 0.0f);
    }

    // tail
    for (; i < n4; i += stride) {
        float4 xv = __ldcs(&x4[i]);
        float4 yv = __ldcs(&y4[i]);
        float d0 = xv.x - yv.x, d1 = xv.y - yv.y;
        float d2 = xv.z - yv.z, d3 = xv.w - yv.w;
        fs0 += fmaxf(d0, 0.0f) + fmaxf(d1, 0.0f)
             + fmaxf(d2, 0.0f) + fmaxf(d3, 0.0f);
        cnt += (d0 > 0.0f) + (d1 > 0.0f) + (d2 > 0.0f) + (d3 > 0.0f);
    }

    float fsum = fs0 + fs1;

    // warp reduce
    #pragma unroll
    for (int off = 16; off > 0; off >>= 1) {
        fsum += __shfl_down_sync(0xFFFFFFFFu, fsum, off);
        cnt  += __shfl_down_sync(0xFFFFFFFFu, cnt,  off);
    }

    __shared__ float        s_sum[8];
    __shared__ unsigned int s_cnt[8];
    __shared__ bool         s_last;
    int lane = threadIdx.x & 31;
    int wid  = threadIdx.x >> 5;
    if (lane == 0) { s_sum[wid] = fsum; s_cnt[wid] = cnt; }
    __syncthreads();

    if (wid == 0) {
        fsum = (lane < 8) ? s_sum[lane] : 0.0f;
        cnt  = (lane < 8) ? s_cnt[lane] : 0u;
        #pragma unroll
        for (int off = 4; off > 0; off >>= 1) {
            fsum += __shfl_down_sync(0xFFFFFFFFu, fsum, off);
            cnt  += __shfl_down_sync(0xFFFFFFFFu, cnt,  off);
        }
        if (lane == 0) {
            atomicAdd(&g_sum, fsum);
            atomicAdd(&g_cnt, (unsigned long long)cnt);
            __threadfence();
            unsigned int t = atomicAdd(&g_ticket, 1u);
            s_last = (t == gridDim.x - 1);
        }
    }
    __syncthreads();

    // Last block: write result, reset globals for next graph replay.
    if (s_last && threadIdx.x == 0) {
        __threadfence();   // make all blocks' atomics visible to this read
        float              fs = g_sum;
        unsigned long long c  = g_cnt;
        out[0] = (c > 0ull) ? (fs / (float)c) : 0.0f;
        g_sum    = 0.0f;
        g_cnt    = 0ull;
        g_ticket = 0u;     // replay boundary orders these before next launch
    }
}

extern "C" void kernel_launch(void* const* d_in, const int* in_sizes, int n_in,
                              void* d_out, int out_size) {
    const float* x = (const float*)d_in[0];
    const float* y = (const float*)d_in[1];
    float* out = (float*)d_out;

    int n  = in_sizes[0];      // 33554432, divisible by 4
    int n4 = n >> 2;

    const int threads = 256;
    const int blocks  = 148 * 8;   // 1184 CTAs -- balanced waves on 148 SMs
    fused_reduce_kernel<<<blocks, threads>>>(
        (const float4*)x, (const float4*)y, n4, out);
}

// round 7
// speedup vs baseline: 1.1317x; 1.0486x over previous
#include <cuda_runtime.h>
#include <cuda_bf16.h>

// Masked mean: mean of (x - y) where x > y, over 32M fp32 elements.
// GB300 has 152 SMs (not B300's 148) -- grid sized 152x8 = 1216 CTAs for
// perfectly balanced waves. 256 thr/CTA, 4x-unrolled grid-stride,
// front-batched x-loads then y-loads (4+4 LDG.128 bursts), __ldcs
// streaming (touch-once). Last-block-done finalize with self-resetting
// __device__ globals (graph-replay safe, single launch).

__device__ float               g_sum;     // zero-initialized at load
__device__ unsigned long long  g_cnt;
__device__ unsigned int        g_ticket;

__global__ __launch_bounds__(256) void fused_reduce_kernel(
    const float4* __restrict__ x4,
    const float4* __restrict__ y4,
    int n4,
    float* __restrict__ out)
{
    float fs0 = 0.0f, fs1 = 0.0f;
    unsigned int cnt = 0;

    const int stride = gridDim.x * blockDim.x;
    int i = blockIdx.x * blockDim.x + threadIdx.x;

    // main loop: 4x unrolled, 4 x-loads batched then 4 y-loads batched
    for (; i + 3 * stride < n4; i += 4 * stride) {
        float4 xa = __ldcs(&x4[i]);
        float4 xb = __ldcs(&x4[i +     stride]);
        float4 xc = __ldcs(&x4[i + 2 * stride]);
        float4 xd = __ldcs(&x4[i + 3 * stride]);
        float4 ya = __ldcs(&y4[i]);
        float4 yb = __ldcs(&y4[i +     stride]);
        float4 yc = __ldcs(&y4[i + 2 * stride]);
        float4 yd = __ldcs(&y4[i + 3 * stride]);

        float a0 = xa.x - ya.x, a1 = xa.y - ya.y, a2 = xa.z - ya.z, a3 = xa.w - ya.w;
        float b0 = xb.x - yb.x, b1 = xb.y - yb.y, b2 = xb.z - yb.z, b3 = xb.w - yb.w;
        float c0 = xc.x - yc.x, c1 = xc.y - yc.y, c2 = xc.z - yc.z, c3 = xc.w - yc.w;
        float e0 = xd.x - yd.x, e1 = xd.y - yd.y, e2 = xd.z - yd.z, e3 = xd.w - yd.w;

        fs0 += fmaxf(a0, 0.0f) + fmaxf(a1, 0.0f) + fmaxf(a2, 0.0f) + fmaxf(a3, 0.0f);
        fs1 += fmaxf(b0, 0.0f) + fmaxf(b1, 0.0f) + fmaxf(b2, 0.0f) + fmaxf(b3, 0.0f);
        fs0 += fmaxf(c0, 0.0f) + fmaxf(c1, 0.0f) + fmaxf(c2, 0.0f) + fmaxf(c3, 0.0f);
        fs1 += fmaxf(e0, 0.0f) + fmaxf(e1, 0.0f) + fmaxf(e2, 0.0f) + fmaxf(e3, 0.0f);

        cnt += (a0 > 0.0f) + (a1 > 0.0f) + (a2 > 0.0f) + (a3 > 0.0f)
             + (b0 > 0.0f) + (b1 > 0.0f) + (b2 > 0.0f) + (b3 > 0.0f)
             + (c0 > 0.0f) + (c1 > 0.0f) + (c2 > 0.0f) + (c3 > 0.0f)
             + (e0 > 0.0f) + (e1 > 0.0f) + (e2 > 0.0f) + (e3 > 0.0f);
    }

    // tail
    for (; i < n4; i += stride) {
        float4 xv = __ldcs(&x4[i]);
        float4 yv = __ldcs(&y4[i]);
        float d0 = xv.x - yv.x, d1 = xv.y - yv.y;
        float d2 = xv.z - yv.z, d3 = xv.w - yv.w;
        fs0 += fmaxf(d0, 0.0f) + fmaxf(d1, 0.0f)
             + fmaxf(d2, 0.0f) + fmaxf(d3, 0.0f);
        cnt += (d0 > 0.0f) + (d1 > 0.0f) + (d2 > 0.0f) + (d3 > 0.0f);
    }

    float fsum = fs0 + fs1;

    // warp reduce
    #pragma unroll
    for (int off = 16; off > 0; off >>= 1) {
        fsum += __shfl_down_sync(0xFFFFFFFFu, fsum, off);
        cnt  += __shfl_down_sync(0xFFFFFFFFu, cnt,  off);
    }

    __shared__ float        s_sum[8];
    __shared__ unsigned int s_cnt[8];
    __shared__ bool         s_last;
    int lane = threadIdx.x & 31;
    int wid  = threadIdx.x >> 5;
    if (lane == 0) { s_sum[wid] = fsum; s_cnt[wid] = cnt; }
    __syncthreads();

    if (wid == 0) {
        fsum = (lane < 8) ? s_sum[lane] : 0.0f;
        cnt  = (lane < 8) ? s_cnt[lane] : 0u;
        #pragma unroll
        for (int off = 4; off > 0; off >>= 1) {
            fsum += __shfl_down_sync(0xFFFFFFFFu, fsum, off);
            cnt  += __shfl_down_sync(0xFFFFFFFFu, cnt,  off);
        }
        if (lane == 0) {
            atomicAdd(&g_sum, fsum);
            atomicAdd(&g_cnt, (unsigned long long)cnt);
            __threadfence();
            unsigned int t = atomicAdd(&g_ticket, 1u);
            s_last = (t == gridDim.x - 1);
        }
    }
    __syncthreads();

    // Last block: write result, reset globals for next graph replay.
    if (s_last && threadIdx.x == 0) {
        __threadfence();   // make all blocks' atomics visible to this read
        float              fs = g_sum;
        unsigned long long c  = g_cnt;
        out[0] = (c > 0ull) ? (fs / (float)c) : 0.0f;
        g_sum    = 0.0f;
        g_cnt    = 0ull;
        g_ticket = 0u;     // replay boundary orders these before next launch
    }
}

extern "C" void kernel_launch(void* const* d_in, const int* in_sizes, int n_in,
                              void* d_out, int out_size) {
    const float* x = (const float*)d_in[0];
    const float* y = (const float*)d_in[1];
    float* out = (float*)d_out;

    int n  = in_sizes[0];      // 33554432, divisible by 4
    int n4 = n >> 2;

    const int threads = 256;
    const int blocks  = 152 * 8;   // 1216 CTAs -- balanced on GB300's 152 SMs
    fused_reduce_kernel<<<blocks, threads>>>(
        (const float4*)x, (const float4*)y, n4, out);
}